// round 1
// baseline (speedup 1.0000x reference)
#include <cuda_runtime.h>
#include <cstdint>

// Problem constants (match reference_code)
#define DFEAT   128   // feature dim
#define KTOP    8     // top-k neighbors per feature
#define DEG     32    // max out-degree
#define OUT_CH  128   // conv out channels
#define IN_CH   9     // conv in channels (K+1)
#define KSZ     9     // conv kernel size (K+1)
#define XOUT    120   // DFEAT - KTOP
#define MAXN    10000

// Scratch (device globals: no allocation allowed in kernel_launch)
__device__ int g_nbr[MAXN * DEG];
__device__ int g_cnt[MAXN];

// ---------------------------------------------------------------------------
// Kernel 1: extract neighbor index sets from the adjacency matrix.
// One block per row; 400MB streamed from HBM. Order within the set does not
// matter (downstream top-k is over values only).
// ---------------------------------------------------------------------------
__global__ void __launch_bounds__(256) nbr_kernel(const int* __restrict__ adj, int n)
{
    int row = blockIdx.x;
    __shared__ int s_cnt;
    __shared__ int s_idx[DEG];
    if (threadIdx.x == 0) s_cnt = 0;
    __syncthreads();

    const int4* rp = reinterpret_cast<const int4*>(adj + (size_t)row * (size_t)n);
    int nvec = n >> 2;  // n is a multiple of 4 here (10000)
    for (int i = threadIdx.x; i < nvec; i += blockDim.x) {
        int4 v = rp[i];
        if (v.x | v.y | v.z | v.w) {
            int base = 4 * i;
            if (v.x) { int p = atomicAdd(&s_cnt, 1); if (p < DEG) s_idx[p] = base;     }
            if (v.y) { int p = atomicAdd(&s_cnt, 1); if (p < DEG) s_idx[p] = base + 1; }
            if (v.z) { int p = atomicAdd(&s_cnt, 1); if (p < DEG) s_idx[p] = base + 2; }
            if (v.w) { int p = atomicAdd(&s_cnt, 1); if (p < DEG) s_idx[p] = base + 3; }
        }
    }
    // tail (n not multiple of 4) — not hit for n=10000, kept for safety
    for (int j = (nvec << 2) + threadIdx.x; j < n; j += blockDim.x) {
        if (adj[(size_t)row * (size_t)n + j]) {
            int p = atomicAdd(&s_cnt, 1); if (p < DEG) s_idx[p] = j;
        }
    }
    __syncthreads();
    int c = min(s_cnt, DEG);
    if (threadIdx.x < DEG)
        g_nbr[row * DEG + threadIdx.x] = (threadIdx.x < c) ? s_idx[threadIdx.x] : 0;
    if (threadIdx.x == 0) g_cnt[row] = c;
}

// ---------------------------------------------------------------------------
// Kernel 2: per-node fused [per-feature top-8 + zero-pad semantics] + Conv1d.
// One block (256 threads) per node.
//   smem: w_sh[128][9][12] (t padded 9->12 for float4), sel[9][128], bias[128]
//   Conv mapping: warp w owns out channels [16w,16w+16); lane L (<30) owns
//   x0 = 4L..4L+3. 64 fp32 accumulators per thread.
// ---------------------------------------------------------------------------
#define WSTRIDE_O 108   // 9*12
#define WSTRIDE_C 12

__global__ void __launch_bounds__(256, 2) conv_kernel(
    const float* __restrict__ feat,
    const float* __restrict__ w,
    const float* __restrict__ bias,
    float* __restrict__ out)
{
    extern __shared__ float smem[];
    float* w_sh = smem;                         // OUT_CH * 108
    float* sel  = w_sh + OUT_CH * WSTRIDE_O;    // IN_CH * DFEAT
    float* b_sh = sel + IN_CH * DFEAT;          // OUT_CH
    __shared__ int s_nbr[DEG];
    __shared__ int s_cnt;

    const int node = blockIdx.x;
    const int tid  = threadIdx.x;

    // Stage weights into padded smem layout [o][c][12]
    for (int i = tid; i < OUT_CH * IN_CH * KSZ; i += 256) {
        int o = i / (IN_CH * KSZ);
        int r = i - o * (IN_CH * KSZ);
        int c = r / KSZ;
        int t = r - c * KSZ;
        w_sh[o * WSTRIDE_O + c * WSTRIDE_C + t] = w[i];
    }
    if (tid < OUT_CH) b_sh[tid] = bias[tid];
    if (tid < DEG)    s_nbr[tid] = g_nbr[node * DEG + tid];
    if (tid == 0)     s_cnt = g_cnt[node];
    __syncthreads();

    const int cnt = s_cnt;

    // ---- Stage 1: per-feature-column top-8 with exact padding semantics ----
    if (tid < DFEAT) {
        const int d = tid;
        float t8[KTOP];
#pragma unroll
        for (int k = 0; k < KTOP; k++) t8[k] = -INFINITY;

        for (int j = 0; j < cnt; j++) {
            float v = feat[(size_t)s_nbr[j] * DFEAT + d];
            if (v > t8[KTOP - 1]) {
                t8[KTOP - 1] = v;
                // one bubble pass restores descending order
#pragma unroll
                for (int k = KTOP - 2; k >= 0; k--) {
                    if (t8[k + 1] > t8[k]) {
                        float tmp = t8[k]; t8[k] = t8[k + 1]; t8[k + 1] = tmp;
                    }
                }
            }
        }
        // reference: -inf (missing) -> 0, then resort descending
#pragma unroll
        for (int k = 0; k < KTOP; k++)
            if (t8[k] == -INFINITY) t8[k] = 0.0f;
        if (cnt < KTOP) {
            // full insertion sort (descending) — only hit on degenerate rows
#pragma unroll
            for (int a = 1; a < KTOP; a++) {
#pragma unroll
                for (int bq = a; bq >= 1; bq--) {
                    if (t8[bq] > t8[bq - 1]) {
                        float tmp = t8[bq - 1]; t8[bq - 1] = t8[bq]; t8[bq] = tmp;
                    }
                }
            }
        }
        sel[0 * DFEAT + d] = feat[(size_t)node * DFEAT + d];
#pragma unroll
        for (int k = 0; k < KTOP; k++) sel[(1 + k) * DFEAT + d] = t8[k];
    }
    __syncthreads();

    // ---- Stage 2: Conv1d ----
    const int warp = tid >> 5;
    const int lane = tid & 31;
    if (lane < 30) {
        const int x0 = lane * 4;
        float acc[16][4];
#pragma unroll
        for (int oi = 0; oi < 16; oi++)
#pragma unroll
            for (int j = 0; j < 4; j++) acc[oi][j] = 0.0f;

        for (int c = 0; c < IN_CH; c++) {
            const float4* sp = reinterpret_cast<const float4*>(&sel[c * DFEAT + x0]);
            float4 s0 = sp[0], s1 = sp[1], s2 = sp[2];
            float sv[12] = { s0.x, s0.y, s0.z, s0.w,
                             s1.x, s1.y, s1.z, s1.w,
                             s2.x, s2.y, s2.z, s2.w };
#pragma unroll
            for (int oi = 0; oi < 16; oi++) {
                const int o = warp * 16 + oi;
                const float4* wp = reinterpret_cast<const float4*>(
                    &w_sh[o * WSTRIDE_O + c * WSTRIDE_C]);
                float4 w0 = wp[0], w1 = wp[1], w2 = wp[2];
                float wv[12] = { w0.x, w0.y, w0.z, w0.w,
                                 w1.x, w1.y, w1.z, w1.w,
                                 w2.x, w2.y, w2.z, w2.w };
#pragma unroll
                for (int t = 0; t < KSZ; t++) {
#pragma unroll
                    for (int j = 0; j < 4; j++)
                        acc[oi][j] += sv[j + t] * wv[t];
                }
            }
        }

        float* op = out + (size_t)node * OUT_CH * XOUT;
#pragma unroll
        for (int oi = 0; oi < 16; oi++) {
            const int o = warp * 16 + oi;
            const float bb = b_sh[o];
            float4 r = make_float4(acc[oi][0] + bb, acc[oi][1] + bb,
                                   acc[oi][2] + bb, acc[oi][3] + bb);
            *reinterpret_cast<float4*>(op + o * XOUT + x0) = r;
        }
    }
}

// ---------------------------------------------------------------------------
extern "C" void kernel_launch(void* const* d_in, const int* in_sizes, int n_in,
                              void* d_out, int out_size)
{
    const float* feat = (const float*)d_in[0];
    const int*   adj  = (const int*)d_in[1];
    const float* w    = (const float*)d_in[2];
    const float* b    = (const float*)d_in[3];
    float*       out  = (float*)d_out;

    int n = in_sizes[0] / DFEAT;          // number of nodes
    if (n > MAXN) n = MAXN;

    const int smem_bytes = (OUT_CH * WSTRIDE_O + IN_CH * DFEAT + OUT_CH) * sizeof(float);
    cudaFuncSetAttribute(conv_kernel, cudaFuncAttributeMaxDynamicSharedMemorySize,
                         smem_bytes);

    nbr_kernel<<<n, 256>>>(adj, n);
    conv_kernel<<<n, 256, smem_bytes>>>(feat, w, b, out);
}